// round 14
// baseline (speedup 1.0000x reference)
#include <cuda_runtime.h>

#define IMG_W  512
#define IMG_H  512
#define IMG_N  (IMG_W * IMG_H)
#define TILE_X 64             /* output columns per CTA */
#define NT     32             /* ONE warp; each thread owns 2 adjacent columns */
#define TILE_Y 64
#define HALO   5
#define NITER  (TILE_Y + 2 * HALO)   /* 74 h-conv rows per tile */
#define ROW_E  76             /* smem row entries: cols x0-6 .. x0+69 */
#define MM_BLOCKS 1024
#define MM_THREADS 256

// Normalized 11-tap Gaussian, sigma=1.5, center at ws/2=5.5 (matches ref).
__device__ constexpr float GW[11] = {
    3.2030000e-04f, 2.9556500e-03f, 1.7487670e-02f, 6.6342420e-02f,
    1.6137299e-01f, 2.5168110e-01f, 2.5168110e-01f, 1.6137299e-01f,
    6.6342420e-02f, 1.7487670e-02f, 2.9556500e-03f
};

typedef unsigned long long u64;

__device__ __forceinline__ u64 pack2(float x, float y) {
    u64 r; asm("mov.b64 %0, {%1, %2};" : "=l"(r) : "f"(x), "f"(y)); return r;
}
__device__ __forceinline__ void unpack2(u64 v, float& x, float& y) {
    asm("mov.b64 {%0, %1}, %2;" : "=f"(x), "=f"(y) : "l"(v));
}
__device__ __forceinline__ u64 fma2(u64 a, u64 b, u64 c) {
    u64 d; asm("fma.rn.f32x2 %0, %1, %2, %3;" : "=l"(d) : "l"(a), "l"(b), "l"(c));
    return d;
}
__device__ __forceinline__ u64 mul2(u64 a, u64 b) {
    u64 d; asm("mul.rn.f32x2 %0, %1, %2;" : "=l"(d) : "l"(a), "l"(b));
    return d;
}

// ---------------------------------------------------------------------------
// Global min/max of img1 -> C1, C2 (single kernel, last-block finalize,
// self-resetting counter => graph-replay safe)
// ---------------------------------------------------------------------------
__device__ float g_blk_max[MM_BLOCKS];
__device__ float g_blk_min[MM_BLOCKS];
__device__ unsigned g_arrive = 0;
__device__ float g_C1, g_C2;

__global__ void __launch_bounds__(MM_THREADS)
minmax_kernel(const float4* __restrict__ x, int n4) {
    float mx = -3.402823466e38f, mn = 3.402823466e38f;
    const int stride = gridDim.x * blockDim.x;
    int i = blockIdx.x * blockDim.x + threadIdx.x;
#pragma unroll 8
    for (; i < n4; i += stride) {
        float4 v = x[i];
        mx = fmaxf(mx, fmaxf(fmaxf(v.x, v.y), fmaxf(v.z, v.w)));
        mn = fminf(mn, fminf(fminf(v.x, v.y), fminf(v.z, v.w)));
    }
#pragma unroll
    for (int o = 16; o > 0; o >>= 1) {
        mx = fmaxf(mx, __shfl_xor_sync(0xFFFFFFFFu, mx, o));
        mn = fminf(mn, __shfl_xor_sync(0xFFFFFFFFu, mn, o));
    }
    __shared__ float smx[8], smn[8];
    __shared__ bool last;
    const int w = threadIdx.x >> 5, l = threadIdx.x & 31;
    if (l == 0) { smx[w] = mx; smn[w] = mn; }
    __syncthreads();
    if (threadIdx.x == 0) {
#pragma unroll
        for (int k = 1; k < MM_THREADS / 32; ++k) {
            mx = fmaxf(mx, smx[k]); mn = fminf(mn, smn[k]);
        }
        g_blk_max[blockIdx.x] = mx;
        g_blk_min[blockIdx.x] = mn;
        __threadfence();
        last = (atomicAdd(&g_arrive, 1u) == (unsigned)(gridDim.x - 1));
    }
    __syncthreads();
    if (last) {
        float fx = -3.402823466e38f, fn = 3.402823466e38f;
#pragma unroll
        for (int k = 0; k < MM_BLOCKS / MM_THREADS; ++k) {
            fx = fmaxf(fx, g_blk_max[threadIdx.x + k * MM_THREADS]);
            fn = fminf(fn, g_blk_min[threadIdx.x + k * MM_THREADS]);
        }
#pragma unroll
        for (int o = 16; o > 0; o >>= 1) {
            fx = fmaxf(fx, __shfl_xor_sync(0xFFFFFFFFu, fx, o));
            fn = fminf(fn, __shfl_xor_sync(0xFFFFFFFFu, fn, o));
        }
        if (l == 0) { smx[w] = fx; smn[w] = fn; }
        __syncthreads();
        if (threadIdx.x == 0) {
#pragma unroll
            for (int k = 1; k < MM_THREADS / 32; ++k) {
                fx = fmaxf(fx, smx[k]); fn = fminf(fn, smn[k]);
            }
            float L = fx - fn;
            if (L == 0.f) L = 5.f;
            g_C1 = (0.01f * L) * (0.01f * L);
            g_C2 = (0.03f * L) * (0.03f * L);
            g_arrive = 0;
        }
    }
}

// ---------------------------------------------------------------------------
// Fused separable-SSIM, 4-channel formulation:
//   convolve (a,b) and (p,q) = ((a+b)^2, (a-b)^2); then
//   sigma1+sigma2 = (Ep+Eq)/2 - mu1^2 - mu2^2,  sigma12 = (Ep-Eq)/4 - mu1*mu2.
// Channels interleaved per column -> one LDS.128 per tap.
// Single-warp CTAs, 2 px/thread, rolling tap temps, one syncwarp/iteration.
// ---------------------------------------------------------------------------
struct RowLd { float2 i1, i2, h1, h2; };

__device__ __forceinline__ RowLd load_row(const float* __restrict__ p1,
                                          const float* __restrict__ p2,
                                          int hy, int x0, int tx) {
    RowLd r;
    r.i1 = make_float2(0.f, 0.f); r.i2 = r.i1; r.h1 = r.i1; r.h2 = r.i1;
    if ((unsigned)hy < (unsigned)IMG_H) {
        const int base = hy * IMG_W;
        const int cI = x0 - 6 + 2 * tx;              // even -> aligned float2
        if ((unsigned)cI < (unsigned)IMG_W) {
            r.i1 = *(const float2*)(p1 + base + cI);
            r.i2 = *(const float2*)(p2 + base + cI);
        }
        if (tx < 6) {
            const int cH = cI + TILE_X;              // j = 64 + 2tx
            if ((unsigned)cH < (unsigned)IMG_W) {
                r.h1 = *(const float2*)(p1 + base + cH);
                r.h2 = *(const float2*)(p2 + base + cH);
            }
        }
    }
    return r;
}

__global__ void __launch_bounds__(NT, 14)
ssim_kernel(const float* __restrict__ img1, const float* __restrict__ img2,
            float* __restrict__ out) {
    const int tx = threadIdx.x;
    const int x0 = blockIdx.x * TILE_X;
    const int y0 = blockIdx.y * TILE_Y;
    const long imgoff = (long)blockIdx.z * IMG_N;
    const float* p1 = img1 + imgoff;
    const float* p2 = img2 + imgoff;
    float* po = out + imgoff;

    const float C1 = g_C1;
    const float C2 = g_C2;

    // two alternating buffer-sets, each a PAIR of rows.
    // entry j <-> image col x0-6+j, j = 0..75; .x = (a,b), .y = (p,q)
    __shared__ ulonglong2 sVS[2][2][ROW_E];

    u64 WW6[6];
#pragma unroll
    for (int k = 0; k < 6; ++k) WW6[k] = pack2(GW[k], GW[k]);

    // per-pixel vertical rings: packed (mu1,mu2) and packed (Ep,Eq)
    u64 rm[2][11], rq[2][11];
#pragma unroll
    for (int k = 0; k < 11; ++k) {
        rm[0][k] = 0ull; rm[1][k] = 0ull;
        rq[0][k] = 0ull; rq[1][k] = 0ull;
    }

    RowLd R0 = load_row(p1, p2, y0 - HALO,     x0, tx);
    RowLd R1 = load_row(p1, p2, y0 - HALO + 1, x0, tx);
    int bs = 0;

    // Publish one row: per column j store {(a,b), ((a+b)^2,(a-b)^2)}.
#define PUBLISH(RR, RL)                                                        \
    do {                                                                       \
        const u64 v0 = pack2((RL).i1.x, (RL).i2.x);                            \
        const u64 v1 = pack2((RL).i1.y, (RL).i2.y);                            \
        const u64 sd0 = pack2((RL).i1.x + (RL).i2.x, (RL).i1.x - (RL).i2.x);   \
        const u64 sd1 = pack2((RL).i1.y + (RL).i2.y, (RL).i1.y - (RL).i2.y);   \
        sVS[bs][RR][2 * tx]     = make_ulonglong2(v0, mul2(sd0, sd0));         \
        sVS[bs][RR][2 * tx + 1] = make_ulonglong2(v1, mul2(sd1, sd1));         \
        if (tx < 6) {                                                          \
            const u64 w0 = pack2((RL).h1.x, (RL).h2.x);                        \
            const u64 w1 = pack2((RL).h1.y, (RL).h2.y);                        \
            const u64 hd0 = pack2((RL).h1.x + (RL).h2.x,                       \
                                  (RL).h1.x - (RL).h2.x);                      \
            const u64 hd1 = pack2((RL).h1.y + (RL).h2.y,                       \
                                  (RL).h1.y - (RL).h2.y);                      \
            sVS[bs][RR][TILE_X + 2 * tx]     =                                 \
                make_ulonglong2(w0, mul2(hd0, hd0));                           \
            sVS[bs][RR][TILE_X + 2 * tx + 1] =                                 \
                make_ulonglong2(w1, mul2(hd1, hd1));                           \
        }                                                                      \
    } while (0)

    // h-pass for BOTH pixels: per tap ONE LDS.128 + 4 fma2, rolling temps.
    // px A taps at j = jb+k, px B at jb+k+1 (jb = 2tx+1).
#define HPASS2(SLOT, RR)                                                       \
    do {                                                                       \
        const int jb = 2 * tx + 1;                                             \
        u64 mA = 0ull, qA = 0ull, mB = 0ull, qB = 0ull;                        \
        ulonglong2 P = sVS[bs][RR][jb];                                        \
        _Pragma("unroll")                                                      \
        for (int k = 0; k < 11; ++k) {                                         \
            const int kk = (k <= 5) ? k : (11 - k);                            \
            const ulonglong2 Cc = sVS[bs][RR][jb + k + 1];                     \
            mA = fma2(P.x,  WW6[kk], mA);                                      \
            qA = fma2(P.y,  WW6[kk], qA);                                      \
            mB = fma2(Cc.x, WW6[kk], mB);                                      \
            qB = fma2(Cc.y, WW6[kk], qB);                                      \
            P = Cc;                                                            \
        }                                                                      \
        rm[0][SLOT] = mA; rq[0][SLOT] = qA;                                    \
        rm[1][SLOT] = mB; rq[1][SLOT] = qB;                                    \
    } while (0)

#define VPX(PX, SLOT, RES)                                                     \
    do {                                                                       \
        u64 M = 0ull, Q = 0ull;                                                \
        _Pragma("unroll")                                                      \
        for (int k = 0; k < 11; ++k) {                                         \
            const int s  = ((SLOT) + 1 + k) % 11;                              \
            const int kk = (k <= 5) ? k : (11 - k);                            \
            M = fma2(rm[PX][s], WW6[kk], M);                                   \
            Q = fma2(rq[PX][s], WW6[kk], Q);                                   \
        }                                                                      \
        float mu1, mu2, Ep, Eq;                                                \
        unpack2(M, mu1, mu2); unpack2(Q, Ep, Eq);                              \
        const float mu1sq = mu1 * mu1;                                         \
        const float mu2sq = mu2 * mu2;                                         \
        const float mu12  = mu1 * mu2;                                         \
        const float musq  = mu1sq + mu2sq;                                     \
        const float sig_s = fmaf(0.5f,  Ep + Eq, -musq);                       \
        const float sig12 = fmaf(0.25f, Ep - Eq, -mu12);                       \
        const float num = fmaf(2.f, mu12, C1) * fmaf(2.f, sig12, C2);          \
        const float den = (musq + C1) * (sig_s + C2);                          \
        RES = __fdividef(num, den);                                            \
    } while (0)

#define VPASS2(SLOT, ROW)                                                      \
    do {                                                                       \
        float2 res;                                                            \
        VPX(0, SLOT, res.x);                                                   \
        VPX(1, SLOT, res.y);                                                   \
        *(float2*)(po + (y0 + (ROW) - 2 * HALO) * IMG_W + x0 + 2 * tx) = res;  \
    } while (0)

    for (int ib = 0; ib < NITER; ib += 22) {
#pragma unroll
        for (int jj = 0; jj < 11; ++jj) {
            const int i0 = ib + 2 * jj;
            if (i0 < NITER) {
                PUBLISH(0, R0);
                PUBLISH(1, R1);
                // prefetch next pair (consumed after next sync)
                R0 = load_row(p1, p2, y0 - HALO + i0 + 2, x0, tx);
                R1 = load_row(p1, p2, y0 - HALO + i0 + 3, x0, tx);
                __syncwarp();    // publish -> consume handshake

                const int s0 = (2 * jj) % 11;       // compile-time
                const int s1 = (2 * jj + 1) % 11;   // compile-time
                HPASS2(s0, 0);
                if (i0 >= 2 * HALO) VPASS2(s0, i0);
                HPASS2(s1, 1);
                if (i0 >= 2 * HALO) VPASS2(s1, i0 + 1);
                bs ^= 1;
                // republish of this buffer set is ordered behind the NEXT
                // iteration's __syncwarp -> one sync per iteration suffices
            }
        }
    }
#undef PUBLISH
#undef HPASS2
#undef VPX
#undef VPASS2
}

// ---------------------------------------------------------------------------
extern "C" void kernel_launch(void* const* d_in, const int* in_sizes, int n_in,
                              void* d_out, int out_size) {
    const float* img1 = (const float*)d_in[0];
    const float* img2 = (const float*)d_in[1];
    float* out = (float*)d_out;
    const int n = in_sizes[0];                 // 32*1*512*512 = 8388608

    minmax_kernel<<<MM_BLOCKS, MM_THREADS>>>((const float4*)img1, n / 4);

    dim3 grid(IMG_W / TILE_X, IMG_H / TILE_Y, n / IMG_N);   // (8, 8, 32)
    ssim_kernel<<<grid, NT>>>(img1, img2, out);
}